// round 4
// baseline (speedup 1.0000x reference)
#include <cuda_runtime.h>
#include <math.h>

static constexpr int T_STEPS = 1460;
static constexpr int G_NUM   = 5000;
static constexpr int HALF    = 2500;   // gauges per "lane"; thread handles g and g+HALF
static constexpr int UH_L    = 15;
static constexpr int PF      = 5;      // 1460 % 5 == 0; prefetch depth

__global__ void __launch_bounds__(32) hmets_kernel(
    const float* __restrict__ x_phy,     // (T, G, 3)
    const float* __restrict__ params,    // (T, G, 20) -- only t = T-1 used
    float* __restrict__ out)             // (T, G)
{
    const int tid = blockIdx.x * blockDim.x + threadIdx.x;
    if (tid >= HALF) return;

    // ---------------- per-gauge parameters (2 gauges per thread) ----------------
    float ddf_min[2], ddf_cap[2], Tbm[2], Kcum[2], fcmin[2], fcsum[2],
          Tbf[2], Kf[2], exp_fe[2], ET_eff[2], c_run[2], c_v2p[2], c_vad[2],
          c_phr[2], Vmax[2], invVmax[2], Ccum[2];
    float uh1[2][UH_L], uh2[2][UH_L];
    float S[2], W[2], C[2], V[2], Ph[2];
    float acc[2][UH_L];

#pragma unroll
    for (int k = 0; k < 2; k++) {
        const int g = tid + k * HALF;
        const float* pp = params + ((long long)(T_STEPS - 1) * G_NUM + g) * 20;
        float r[20];
#pragma unroll
        for (int i = 0; i < 20; i++) r[i] = 1.0f / (1.0f + expf(-pp[i]));

        ddf_min[k] = r[0] * 20.0f;
        const float ddf_pls = r[1] * 20.0f;
        Tbm[k]     = -2.0f  + r[2] * 5.0f;
        Kcum[k]    = 0.01f  + r[3] * 0.19f;
        fcmin[k]   = r[4] * 0.1f;
        const float fcminp = 0.01f + r[5] * 0.24f;
        Ccum[k]    = 0.005f + r[6] * 0.045f;
        Tbf[k]     = -5.0f  + r[7] * 7.0f;
        Kf[k]      = r[8] * 5.0f;
        exp_fe[k]  = r[9];
        ET_eff[k]  = r[10] * 3.0f;
        c_run[k]   = r[11];
        c_v2p[k]   = 1e-5f  + r[12] * (0.02f - 1e-5f);
        c_vad[k]   = r[13] * 0.1f;
        c_phr[k]   = 1e-5f  + r[14] * (0.01f - 1e-5f);
        Vmax[k]    = 0.001f + r[15] * (500.0f - 0.001f);

        const float a1 = 0.3f  + r[16] * (20.0f - 0.3f);
        const float b1 = 0.01f + r[17] * (5.0f  - 0.01f);
        const float a2 = 0.5f  + r[18] * (13.0f - 0.5f);
        const float b2 = 0.15f + r[19] * (1.5f  - 0.15f);

        ddf_cap[k] = ddf_min[k] + ddf_pls;
        fcsum[k]   = fcmin[k] + fcminp;
        invVmax[k] = 1.0f / Vmax[k];

        float s1 = 0.0f, s2 = 0.0f;
#pragma unroll
        for (int l = 0; l < UH_L; l++) {
            float tt = (float)l + 0.5f;
            float w1 = powf(tt, a1 - 1.0f) * expf(-tt / b1);
            float w2 = powf(tt, a2 - 1.0f) * expf(-tt / b2);
            uh1[k][l] = w1; uh2[k][l] = w2; s1 += w1; s2 += w2;
        }
        const float i1 = 1.0f / s1, i2 = 1.0f / s2;
#pragma unroll
        for (int l = 0; l < UH_L; l++) { uh1[k][l] *= i1; uh2[k][l] *= i2; }

        S[k] = 1e-5f; W[k] = 1e-5f; C[k] = 1e-5f; V[k] = 0.5f * Vmax[k]; Ph[k] = 1e-5f;
#pragma unroll
        for (int l = 0; l < UH_L; l++) acc[k][l] = 0.0f;
    }

    // ---------------- software-pipelined forcing prefetch ----------------
    // gauge A at xb[0..2], gauge B at xb[HALF*3 .. HALF*3+2] (immediate offset)
    constexpr int XSTRIDE = 3 * G_NUM;       // floats per timestep row
    constexpr int BOFF    = 3 * HALF;        // gauge-B offset within a row

    const float* xb = x_phy + tid * 3;
    float bp[2][PF], bt[2][PF], be[2][PF];
#pragma unroll
    for (int j = 0; j < PF; j++) {
        const float* q = xb + j * XSTRIDE;
        bp[0][j] = q[0];        bt[0][j] = q[1];        be[0][j] = q[2];
        bp[1][j] = q[BOFF + 0]; bt[1][j] = q[BOFF + 1]; be[1][j] = q[BOFF + 2];
    }
    const float* qp = xb + PF * XSTRIDE;     // next row to prefetch
    float* ob = out + tid;

    for (int tb = 0; tb < T_STEPS; tb += PF) {
#pragma unroll
        for (int j = 0; j < PF; j++) {
            const int t = tb + j;

            float Pp[2] = { bp[0][j], bp[1][j] };
            float Tt[2] = { bt[0][j], bt[1][j] };
            float PE[2] = { be[0][j], be[1][j] };

            // prefetch row t+PF into the consumed slot
            if (t + PF < T_STEPS) {
                bp[0][j] = qp[0];        bt[0][j] = qp[1];        be[0][j] = qp[2];
                bp[1][j] = qp[BOFF + 0]; bt[1][j] = qp[BOFF + 1]; be[1][j] = qp[BOFF + 2];
            }
            qp += XSTRIDE;

            float qout[2];
#pragma unroll
            for (int k = 0; k < 2; k++) {
                // -------- HMETS step --------
                const float rain = (Tt[k] >= 0.0f) ? Pp[k] : 0.0f;
                const float snow = (Tt[k] <  0.0f) ? Pp[k] : 0.0f;

                const float pot_fr = Kf[k] * __powf(fmaxf(Tbf[k] - Tt[k], 1e-5f), exp_fe[k]);
                const float fr = fminf(pot_fr, W[k]);
                W[k] -= fr;
                S[k] += fr;

                const float ddf  = fminf(ddf_cap[k], ddf_min[k] * (1.0f + Kcum[k] * C[k]));
                const float melt = fminf(fmaxf(ddf * (Tt[k] - Tbm[k]), 0.0f), S[k] + snow);
                S[k] = S[k] + snow - melt;
                C[k] = (S[k] > 1e-5f) ? (C[k] + melt) : 0.0f;

                const float wrf  = fmaxf(fcsum[k] * (1.0f - Ccum[k] * C[k]), fcmin[k]);
                const float wr   = wrf * S[k];
                const float wtmp = W[k] + melt + rain;
                const float wa   = fmaxf(wtmp - wr, 0.0f);
                W[k] = (wa > 0.0f) ? wr : wtmp;

                const float RET   = ET_eff[k] * PE[k];
                const float ratio = V[k] * invVmax[k];
                const float ht0   = c_run[k] * ratio * wa;
                const float infil = fmaxf(wa - ht0 - RET, 0.0f);
                float ht1         = c_run[k] * ratio * ratio * infil;
                const float ht2   = c_vad[k] * V[k];
                const float v2p   = c_v2p[k] * V[k];
                V[k] = V[k] + (infil - ht1) - ht2 - v2p;
                const float over  = fmaxf(V[k] - Vmax[k], 0.0f);
                V[k] -= over;
                ht1 += over;
                Ph[k] += v2p;
                const float ht3 = c_phr[k] * Ph[k];
                Ph[k] -= ht3;

                // -------- fused UH convolution (scatter form) --------
                qout[k] = acc[k][0] + ht0 * uh1[k][0] + ht1 * uh2[k][0] + (ht2 + ht3);
#pragma unroll
                for (int l = 0; l < UH_L - 1; l++)
                    acc[k][l] = acc[k][l + 1] + ht0 * uh1[k][l + 1] + ht1 * uh2[k][l + 1];
                acc[k][UH_L - 1] = 0.0f;
            }

            ob[t * G_NUM]        = qout[0];
            ob[t * G_NUM + HALF] = qout[1];
        }
    }
}

extern "C" void kernel_launch(void* const* d_in, const int* in_sizes, int n_in,
                              void* d_out, int out_size) {
    const float* x_phy  = (const float*)d_in[0];
    const float* params = (const float*)d_in[1];
    float* out = (float*)d_out;
    (void)in_sizes; (void)n_in; (void)out_size;
    hmets_kernel<<<(HALF + 31) / 32, 32>>>(x_phy, params, out);
}